// round 13
// baseline (speedup 1.0000x reference)
#include <cuda_runtime.h>
#include <cuda_fp16.h>
#include <cstdint>

#define B_SZ   4096
#define IN_SZ  1024
#define HID_SZ 2048
#define OUT_SZ 512

// ---------------- scratch (device globals; no allocation) ----------------
__device__ __align__(128) __half g_At[(size_t)B_SZ * IN_SZ];    // psp^T  [B][IN]  fp16
__device__ __align__(128) __half g_Wh[(size_t)HID_SZ * IN_SZ];  // W_h    [HID][IN]
__device__ __align__(128) __half g_Wo[(size_t)OUT_SZ * HID_SZ]; // W_o    [OUT][HID]
__device__ __align__(128) __half g_R [(size_t)B_SZ * HID_SZ];   // rate   [B][HID]

// ---------------- helpers ----------------
__device__ __forceinline__ uint32_t su32(const void* p) {
    uint32_t a;
    asm("{ .reg .u64 t; cvta.to.shared.u64 t, %1; cvt.u32.u64 %0, t; }" : "=r"(a) : "l"(p));
    return a;
}
__device__ __forceinline__ void cp16(uint32_t s, const void* g) {
    asm volatile("cp.async.cg.shared.global [%0], [%1], 16;" :: "r"(s), "l"(g));
}
__device__ __forceinline__ void cp_arrive(uint32_t mbar) {
    asm volatile("cp.async.mbarrier.arrive.noinc.shared.b64 [%0];" :: "r"(mbar) : "memory");
}
__device__ __forceinline__ void mbar_init(uint32_t a, uint32_t cnt) {
    asm volatile("mbarrier.init.shared.b64 [%0], %1;" :: "r"(a), "r"(cnt) : "memory");
}
__device__ __forceinline__ void mbar_arrive(uint32_t a) {
    asm volatile("mbarrier.arrive.shared.b64 _, [%0];" :: "r"(a) : "memory");
}
__device__ __forceinline__ void mbar_wait(uint32_t mbar, uint32_t parity) {
    asm volatile(
        "{\n\t.reg .pred P;\n"
        "LAB_W%=:\n\t"
        "mbarrier.try_wait.parity.acquire.cta.shared::cta.b64 P, [%0], %1, 0x989680;\n\t"
        "@!P bra LAB_W%=;\n\t"
        "}"
        :: "r"(mbar), "r"(parity) : "memory");
}

#define LDSM4(r, addr) \
    asm volatile("ldmatrix.sync.aligned.m8n8.x4.shared.b16 {%0,%1,%2,%3}, [%4];" \
        : "=r"((r)[0]), "=r"((r)[1]), "=r"((r)[2]), "=r"((r)[3]) : "r"(addr))

#define MMA(d, a, b0, b1) \
    asm volatile("mma.sync.aligned.m16n8k16.row.col.f32.f16.f16.f32 " \
        "{%0,%1,%2,%3},{%4,%5,%6,%7},{%8,%9},{%0,%1,%2,%3};" \
        : "+f"((d)[0]), "+f"((d)[1]), "+f"((d)[2]), "+f"((d)[3]) \
        : "r"((a)[0]), "r"((a)[1]), "r"((a)[2]), "r"((a)[3]), "r"(b0), "r"(b1))

// ---------------- fused GEMM: MTx128 CTA tile, k-chunk 32, 6-stage mbarrier ring ----
// smem tile layout: [rows][64 bytes]; 16B-chunk swizzle: ch ^= (row>>1) & 3
// Warps: 2 (m) x 4 (n). Warp tile: (MT/2) x 32.
// Deep ring: free-wait for chunk kc+6 gates on chunk kc -> up to 5 chunks of drift.
// EPI=0: rate = 0.35*sigmoid((6/7)*(acc + b)) -> g_R fp16
// EPI=1: out  = 0.35*sigmoid(0.75*acc + 0.75*b + 0.125*label) -> out fp32
template<int KDIM, int EPI, int MT>
__global__ __launch_bounds__(256, 2)
void k_gemm(const float* __restrict__ bias, const float* __restrict__ label,
            float* __restrict__ out)
{
    constexpr int NMT = MT / 32;                       // per-warp m16 tiles
    constexpr uint32_t AOFF  = 0u;
    constexpr uint32_t BOFF  = (uint32_t)MT * 64u;     // B region in stage
    constexpr uint32_t STAGE = BOFF + 128u * 64u;      // + B (128 rows x 64B)
    constexpr uint32_t MBAR  = 6u * STAGE;             // mbarrier block

    const __half* __restrict__ Ag = (EPI == 0) ? g_At : g_R;
    const __half* __restrict__ Bg = (EPI == 0) ? g_Wh : g_Wo;

    extern __shared__ __align__(1024) uint8_t smem[];
    const uint32_t sbase = su32(smem);
    const uint32_t mbF = sbase + MBAR;        // full[s] at +8s
    const uint32_t mbE = sbase + MBAR + 48;   // free[s] at +8s

    const int tid = threadIdx.x, lane = tid & 31, wid = tid >> 5;
    const int m0 = blockIdx.x * MT, n0 = blockIdx.y * 128;
    const int wm0 = (wid >> 2) * (MT / 2), wn0 = (wid & 3) * 32;

    if (tid == 0) {
#pragma unroll
        for (int s = 0; s < 6; s++) {
            mbar_init(mbF + 8u * s, 256);
            mbar_init(mbE + 8u * s, 256);
        }
    }
    __syncthreads();

    // ---- cp.async mapping: 64B rows, 4 x 16B chunks/row; 256 thr = 64 rows/pass ----
    const int lrow = tid >> 2;           // 0..63
    const int lch  = tid & 3;            // 16B chunk in row
    // (row>>1)&3 is pass-invariant (rows step by 64)
    const uint32_t sOff = (uint32_t)(lrow * 64 + ((lch ^ ((lrow >> 1) & 3)) << 4));
    const __half* pA = Ag + (size_t)(m0 + lrow) * KDIM + lch * 8;
    const __half* pB = Bg + (size_t)(n0 + lrow) * KDIM + lch * 8;
    const uint32_t uA = sbase + AOFF + sOff;
    const uint32_t uB = sbase + BOFF + sOff;

    // ---- ldmatrix per-thread bases ----
    const int ach = lane >> 4;                   // 0/1: 16B col half of k16
    const int bch = (lane >> 3) & 1;
    uint32_t aBase[NMT], aSw[NMT], bBase[2], bSw[2];
#pragma unroll
    for (int mt = 0; mt < NMT; mt++) {
        const int r = wm0 + (lane & 15) + mt * 16;
        aBase[mt] = sbase + AOFF + (uint32_t)(r * 64);
        aSw[mt] = (uint32_t)((r >> 1) & 3);
    }
#pragma unroll
    for (int nt = 0; nt < 2; nt++) {
        const int r = wn0 + (lane & 7) + ((lane >> 4) << 3) + nt * 16;
        bBase[nt] = sbase + BOFF + (uint32_t)(r * 64);
        bSw[nt] = (uint32_t)((r >> 1) & 3);
    }

    float c[NMT][4][4];
#pragma unroll
    for (int i = 0; i < NMT; i++)
#pragma unroll
        for (int j = 0; j < 4; j++)
#pragma unroll
            for (int r = 0; r < 4; r++) c[i][j][r] = 0.0f;

    auto produce = [&](int kc) {
        const int s = kc % 6;
        const size_t ko = (size_t)kc * 32;
        const uint32_t so = (uint32_t)s * STAGE;
#pragma unroll
        for (int j = 0; j < MT / 64; j++)          // A rows, 64/pass
            cp16(uA + so + j * 4096u, pA + ko + (size_t)j * 64 * KDIM);
#pragma unroll
        for (int j = 0; j < 2; j++)                // B rows (128), 64/pass
            cp16(uB + so + j * 4096u, pB + ko + (size_t)j * 64 * KDIM);
        cp_arrive(mbF + 8u * s);
    };

    constexpr int NC = KDIM / 32;
#pragma unroll
    for (int k0 = 0; k0 < 6; k0++) produce(k0);    // fill all 6 stages
#pragma unroll 1
    for (int kc = 0; kc < NC; kc++) {
        const int s = kc % 6;
        mbar_wait(mbF + 8u * s, (uint32_t)((kc / 6) & 1));
        const uint32_t so = (uint32_t)s * STAGE;
#pragma unroll
        for (int kt = 0; kt < 2; kt++) {
            uint32_t af[NMT][4], bf[2][4];
#pragma unroll
            for (int mt = 0; mt < NMT; mt++) {
                const uint32_t ch = (uint32_t)(kt * 2 + ach) ^ aSw[mt];
                LDSM4(af[mt], aBase[mt] + so + (ch << 4));
            }
#pragma unroll
            for (int nt = 0; nt < 2; nt++) {
                const uint32_t ch = (uint32_t)(kt * 2 + bch) ^ bSw[nt];
                LDSM4(bf[nt], bBase[nt] + so + (ch << 4));
            }
#pragma unroll
            for (int mt = 0; mt < NMT; mt++)
#pragma unroll
                for (int n8 = 0; n8 < 4; n8++)
                    MMA(c[mt][n8], af[mt], bf[n8 >> 1][(n8 & 1) * 2],
                                            bf[n8 >> 1][(n8 & 1) * 2 + 1]);
        }
        mbar_arrive(mbE + 8u * s);
        const int kn = kc + 6;
        if (kn < NC) {
            mbar_wait(mbE + 8u * s, (uint32_t)((kc / 6) & 1));
            produce(kn);
        }
    }

    // ---- epilogue ----
    const int mrow = m0 + wm0 + (lane >> 2);
    const int ncol = n0 + wn0 + 2 * (lane & 3);
#pragma unroll
    for (int n8 = 0; n8 < 4; n8++) {
        const int n = ncol + n8 * 8;
        const float b0 = bias[n], b1 = bias[n + 1];
#pragma unroll
        for (int mt = 0; mt < NMT; mt++) {
            const int m = mrow + mt * 16;
            if (EPI == 0) {
                const float S = 6.0f / 7.0f;
#pragma unroll
                for (int h = 0; h < 2; h++) {   // rows m, m+8
                    const float v0 = S * (c[mt][n8][2 * h]     + b0);
                    const float v1 = S * (c[mt][n8][2 * h + 1] + b1);
                    const __half2 r = __floats2half2_rn(0.35f / (1.0f + __expf(-v0)),
                                                        0.35f / (1.0f + __expf(-v1)));
                    *reinterpret_cast<__half2*>(g_R + (size_t)(m + 8 * h) * HID_SZ + n) = r;
                }
            } else {
#pragma unroll
                for (int h = 0; h < 2; h++) {
                    const int mm = m + 8 * h;
                    const float2 lb = *reinterpret_cast<const float2*>(
                        label + (size_t)mm * OUT_SZ + n);
                    const float v0 = 0.75f * c[mt][n8][2 * h]     + 0.75f * b0 + 0.125f * lb.x;
                    const float v1 = 0.75f * c[mt][n8][2 * h + 1] + 0.75f * b1 + 0.125f * lb.y;
                    float2 o;
                    o.x = 0.35f / (1.0f + __expf(-v0));
                    o.y = 0.35f / (1.0f + __expf(-v1));
                    *reinterpret_cast<float2*>(out + (size_t)mm * OUT_SZ + n) = o;
                }
            }
        }
    }
}

// ================= prep, 3 launches so ncu replay position 3 = GEMM1 ================
__global__ void k_tr(const float* __restrict__ psp) {
    constexpr int NBB = B_SZ / 128;                      // 32 b-tiles
    __shared__ float t[32][133];
    const int bid = blockIdx.x, tid = threadIdx.x;
    const int b0 = (bid % NBB) * 128;
    const int k0 = (bid / NBB) * 32;
#pragma unroll
    for (int i = 0; i < 4; i++) {
        const int idx = tid + i * 256;
        const int r = idx >> 5, cc = idx & 31;
        const float4 v = *reinterpret_cast<const float4*>(
            psp + (size_t)(k0 + r) * B_SZ + b0 + cc * 4);
        t[r][cc * 4 + 0] = v.x; t[r][cc * 4 + 1] = v.y;
        t[r][cc * 4 + 2] = v.z; t[r][cc * 4 + 3] = v.w;
    }
    __syncthreads();
#pragma unroll
    for (int i = 0; i < 2; i++) {
        const int idx = tid + i * 256;
        const int b = idx >> 2, kc = idx & 3;
        __half2 h[4];
#pragma unroll
        for (int j = 0; j < 4; j++)
            h[j] = __floats2half2_rn(t[kc * 8 + 2 * j][b], t[kc * 8 + 2 * j + 1][b]);
        *reinterpret_cast<uint4*>(g_At + (size_t)(b0 + b) * IN_SZ + k0 + kc * 8) =
            *reinterpret_cast<uint4*>(h);
    }
}

__global__ void k_cvt(const float4* __restrict__ src, int sel, int n4) {
    const int base = blockIdx.x * 1024 + threadIdx.x;
    __half* dst = sel ? g_Wo : g_Wh;
#pragma unroll
    for (int j = 0; j < 4; j++) {
        const int i = base + j * 256;
        if (i >= n4) continue;
        const float4 v = src[i];
        const __half2 h0 = __floats2half2_rn(v.x, v.y);
        const __half2 h1 = __floats2half2_rn(v.z, v.w);
        uint2 u;
        u.x = *reinterpret_cast<const uint32_t*>(&h0);
        u.y = *reinterpret_cast<const uint32_t*>(&h1);
        *reinterpret_cast<uint2*>(dst + (size_t)i * 4) = u;
    }
}

// ---------------- launcher ----------------
extern "C" void kernel_launch(void* const* d_in, const int* in_sizes, int n_in,
                              void* d_out, int out_size) {
    const float* psp   = (const float*)d_in[0];  // [1024, 4096]
    const float* label = (const float*)d_in[1];  // [4096, 512]
    const float* W_h   = (const float*)d_in[2];  // [2048, 1024]
    const float* b_h   = (const float*)d_in[3];  // [2048]
    const float* W_o   = (const float*)d_in[4];  // [512, 2048]
    const float* b_o   = (const float*)d_in[5];  // [512]
    float* out = (float*)d_out;                  // [4096, 512]

    const int SMEM1 = 6 * (128 * 64 + 128 * 64) + 128;   // 98432
    const int SMEM2 = 6 * (64 * 64 + 128 * 64) + 128;    // 73856
    cudaFuncSetAttribute(k_gemm<IN_SZ, 0, 128>, cudaFuncAttributeMaxDynamicSharedMemorySize, SMEM1);
    cudaFuncSetAttribute(k_gemm<HID_SZ, 1, 64>, cudaFuncAttributeMaxDynamicSharedMemorySize, SMEM2);

    k_tr<<<(B_SZ / 128) * (IN_SZ / 32), 256>>>(psp);
    k_cvt<<<HID_SZ * IN_SZ / 4 / 1024, 256>>>((const float4*)W_h, 0, HID_SZ * IN_SZ / 4);
    k_cvt<<<OUT_SZ * HID_SZ / 4 / 1024, 256>>>((const float4*)W_o, 1, OUT_SZ * HID_SZ / 4);

    k_gemm<IN_SZ,  0, 128><<<dim3(B_SZ / 128, HID_SZ / 128), 256, SMEM1>>>(b_h, nullptr, nullptr);
    k_gemm<HID_SZ, 1, 64 ><<<dim3(B_SZ / 64,  OUT_SZ / 128), 256, SMEM2>>>(b_o, label, out);
}

// round 14
// speedup vs baseline: 1.0933x; 1.0933x over previous
#include <cuda_runtime.h>
#include <cuda_fp16.h>
#include <cstdint>

#define B_SZ   4096
#define IN_SZ  1024
#define HID_SZ 2048
#define OUT_SZ 512

// ---------------- scratch (device globals; no allocation) ----------------
__device__ __align__(128) __half g_At[(size_t)B_SZ * IN_SZ];    // psp^T  [B][IN]  fp16
__device__ __align__(128) __half g_Wh[(size_t)HID_SZ * IN_SZ];  // W_h    [HID][IN]
__device__ __align__(128) __half g_Wo[(size_t)OUT_SZ * HID_SZ]; // W_o    [OUT][HID]
__device__ __align__(128) __half g_R [(size_t)B_SZ * HID_SZ];   // rate   [B][HID]

// ---------------- helpers ----------------
__device__ __forceinline__ uint32_t su32(const void* p) {
    uint32_t a;
    asm("{ .reg .u64 t; cvta.to.shared.u64 t, %1; cvt.u32.u64 %0, t; }" : "=r"(a) : "l"(p));
    return a;
}
__device__ __forceinline__ void cp16(uint32_t s, const void* g) {
    asm volatile("cp.async.cg.shared.global [%0], [%1], 16;" :: "r"(s), "l"(g));
}
__device__ __forceinline__ void cp_arrive(uint32_t mbar) {
    asm volatile("cp.async.mbarrier.arrive.noinc.shared.b64 [%0];" :: "r"(mbar) : "memory");
}
__device__ __forceinline__ void mbar_init(uint32_t a, uint32_t cnt) {
    asm volatile("mbarrier.init.shared.b64 [%0], %1;" :: "r"(a), "r"(cnt) : "memory");
}
__device__ __forceinline__ void mbar_arrive(uint32_t a) {
    asm volatile("mbarrier.arrive.shared.b64 _, [%0];" :: "r"(a) : "memory");
}
__device__ __forceinline__ void mbar_wait(uint32_t mbar, uint32_t parity) {
    asm volatile(
        "{\n\t.reg .pred P;\n"
        "LAB_W%=:\n\t"
        "mbarrier.try_wait.parity.acquire.cta.shared::cta.b64 P, [%0], %1, 0x989680;\n\t"
        "@!P bra LAB_W%=;\n\t"
        "}"
        :: "r"(mbar), "r"(parity) : "memory");
}

#define LDSM4(r, addr) \
    asm volatile("ldmatrix.sync.aligned.m8n8.x4.shared.b16 {%0,%1,%2,%3}, [%4];" \
        : "=r"((r)[0]), "=r"((r)[1]), "=r"((r)[2]), "=r"((r)[3]) : "r"(addr))

#define MMA(d, a, b0, b1) \
    asm volatile("mma.sync.aligned.m16n8k16.row.col.f32.f16.f16.f32 " \
        "{%0,%1,%2,%3},{%4,%5,%6,%7},{%8,%9},{%0,%1,%2,%3};" \
        : "+f"((d)[0]), "+f"((d)[1]), "+f"((d)[2]), "+f"((d)[3]) \
        : "r"((a)[0]), "r"((a)[1]), "r"((a)[2]), "r"((a)[3]), "r"(b0), "r"(b1))

// ---------------- fused GEMM: MTx128 CTA tile, k-chunk 64, 3-stage mbarrier ring ----
// smem tile layout: [rows][128 bytes]; 16B-chunk swizzle: ch ^= (row & 7)
// Warps: 2 (m) x 4 (n). Warp tile: (MT/2) x 32.
// full[s]: count 256 (per-thread cp.async group completion)
// free[s]: count 8   (one arrive per warp after consumption)
// EPI=0: rate = 0.35*sigmoid((6/7)*(acc + b)) -> g_R fp16
// EPI=1: out  = 0.35*sigmoid(0.75*acc + 0.75*b + 0.125*label) -> out fp32
template<int KDIM, int EPI, int MT>
__global__ __launch_bounds__(256, 2)
void k_gemm(const float* __restrict__ bias, const float* __restrict__ label,
            float* __restrict__ out)
{
    constexpr int NMT = MT / 32;                       // per-warp m16 tiles
    constexpr uint32_t BOFF  = (uint32_t)MT * 128u;    // B tile offset in stage
    constexpr uint32_t STAGE = BOFF + 16384u;          // stage size
    constexpr uint32_t MBAR  = 3u * STAGE;             // mbarrier block

    const __half* __restrict__ Ag = (EPI == 0) ? g_At : g_R;
    const __half* __restrict__ Bg = (EPI == 0) ? g_Wh : g_Wo;

    extern __shared__ __align__(1024) uint8_t smem[];
    const uint32_t sbase = su32(smem);
    const uint32_t mbF = sbase + MBAR;        // full[s] at +8s
    const uint32_t mbE = sbase + MBAR + 24;   // free[s] at +8s

    const int tid = threadIdx.x, lane = tid & 31, wid = tid >> 5;
    const int m0 = blockIdx.x * MT, n0 = blockIdx.y * 128;
    const int wm0 = (wid >> 2) * (MT / 2), wn0 = (wid & 3) * 32;

    if (tid == 0) {
#pragma unroll
        for (int s = 0; s < 3; s++) {
            mbar_init(mbF + 8u * s, 256);
            mbar_init(mbE + 8u * s, 8);
        }
    }
    __syncthreads();

    // ---- cp.async mapping ----
    const int lrow = tid >> 3;           // 0..31 (plus 32*j)
    const int lch  = tid & 7;            // 16B chunk in row
    const uint32_t sOff = (uint32_t)(lrow * 128 + ((lch ^ (lrow & 7)) << 4));
    const __half* pA = Ag + (size_t)(m0 + lrow) * KDIM + lch * 8;
    const __half* pB = Bg + (size_t)(n0 + lrow) * KDIM + lch * 8;
    const uint32_t uA = sbase + sOff;
    const uint32_t uB = sbase + BOFF + sOff;

    // ---- ldmatrix per-thread bases ----
    const int ach = lane >> 4;
    const int bch = (lane >> 3) & 1;
    uint32_t aBase[NMT], aSw[NMT], bBase[2], bSw[2];
#pragma unroll
    for (int mt = 0; mt < NMT; mt++) {
        const int r = wm0 + (lane & 15) + mt * 16;
        aBase[mt] = sbase + (uint32_t)(r * 128);
        aSw[mt] = (uint32_t)(r & 7);
    }
#pragma unroll
    for (int nt = 0; nt < 2; nt++) {
        const int r = wn0 + (lane & 7) + ((lane >> 4) << 3) + nt * 16;
        bBase[nt] = sbase + BOFF + (uint32_t)(r * 128);
        bSw[nt] = (uint32_t)(r & 7);
    }

    float c[NMT][4][4];
#pragma unroll
    for (int i = 0; i < NMT; i++)
#pragma unroll
        for (int j = 0; j < 4; j++)
#pragma unroll
            for (int r = 0; r < 4; r++) c[i][j][r] = 0.0f;

    auto produce = [&](int kc) {
        const int s = kc % 3;
        const size_t ko = (size_t)kc * 64;
        const uint32_t so = (uint32_t)s * STAGE;
#pragma unroll
        for (int j = 0; j < MT / 32; j++)
            cp16(uA + so + j * 4096u, pA + ko + (size_t)j * 32 * KDIM);
#pragma unroll
        for (int j = 0; j < 4; j++)
            cp16(uB + so + j * 4096u, pB + ko + (size_t)j * 32 * KDIM);
        cp_arrive(mbF + 8u * s);
    };

    constexpr int NC = KDIM / 64;
    produce(0);
    produce(1);
    produce(2);
#pragma unroll 1
    for (int kc = 0; kc < NC; kc++) {
        const int s = kc % 3;
        mbar_wait(mbF + 8u * s, (uint32_t)((kc / 3) & 1));
        const uint32_t so = (uint32_t)s * STAGE;
#pragma unroll
        for (int kt = 0; kt < 4; kt++) {
            uint32_t af[NMT][4], bf[2][4];
#pragma unroll
            for (int mt = 0; mt < NMT; mt++) {
                const uint32_t ch = (uint32_t)(kt * 2 + ach) ^ aSw[mt];
                LDSM4(af[mt], aBase[mt] + so + (ch << 4));
            }
#pragma unroll
            for (int nt = 0; nt < 2; nt++) {
                const uint32_t ch = (uint32_t)(kt * 2 + bch) ^ bSw[nt];
                LDSM4(bf[nt], bBase[nt] + so + (ch << 4));
            }
#pragma unroll
            for (int mt = 0; mt < NMT; mt++)
#pragma unroll
                for (int n8 = 0; n8 < 4; n8++)
                    MMA(c[mt][n8], af[mt], bf[n8 >> 1][(n8 & 1) * 2],
                                            bf[n8 >> 1][(n8 & 1) * 2 + 1]);
        }
        __syncwarp();
        if (lane == 0) mbar_arrive(mbE + 8u * s);     // one arrive per warp (count 8)
        const int kn = kc + 3;
        if (kn < NC) {
            mbar_wait(mbE + 8u * s, (uint32_t)((kc / 3) & 1));
            produce(kn);
        }
    }

    // ---- epilogue ----
    const int mrow = m0 + wm0 + (lane >> 2);
    const int ncol = n0 + wn0 + 2 * (lane & 3);
#pragma unroll
    for (int n8 = 0; n8 < 4; n8++) {
        const int n = ncol + n8 * 8;
        const float b0 = bias[n], b1 = bias[n + 1];
#pragma unroll
        for (int mt = 0; mt < NMT; mt++) {
            const int m = mrow + mt * 16;
            if (EPI == 0) {
                const float S = 6.0f / 7.0f;
#pragma unroll
                for (int h = 0; h < 2; h++) {   // rows m, m+8
                    const float v0 = S * (c[mt][n8][2 * h]     + b0);
                    const float v1 = S * (c[mt][n8][2 * h + 1] + b1);
                    const __half2 r = __floats2half2_rn(0.35f / (1.0f + __expf(-v0)),
                                                        0.35f / (1.0f + __expf(-v1)));
                    *reinterpret_cast<__half2*>(g_R + (size_t)(m + 8 * h) * HID_SZ + n) = r;
                }
            } else {
#pragma unroll
                for (int h = 0; h < 2; h++) {
                    const int mm = m + 8 * h;
                    const float2 lb = *reinterpret_cast<const float2*>(
                        label + (size_t)mm * OUT_SZ + n);
                    const float v0 = 0.75f * c[mt][n8][2 * h]     + 0.75f * b0 + 0.125f * lb.x;
                    const float v1 = 0.75f * c[mt][n8][2 * h + 1] + 0.75f * b1 + 0.125f * lb.y;
                    float2 o;
                    o.x = 0.35f / (1.0f + __expf(-v0));
                    o.y = 0.35f / (1.0f + __expf(-v1));
                    *reinterpret_cast<float2*>(out + (size_t)mm * OUT_SZ + n) = o;
                }
            }
        }
    }
}

// ---------------- prep (single launch): psp transpose + both weight converts --------
__global__ void k_prep(const float* __restrict__ psp,
                       const float4* __restrict__ Wh, const float4* __restrict__ Wo) {
    constexpr int NBB = B_SZ / 128;                      // 32 b-tiles
    constexpr int NT_BLK = NBB * (IN_SZ / 32);           // 1024 transpose blocks
    constexpr int N4H = HID_SZ * IN_SZ / 4;              // 524288
    constexpr int N4O = OUT_SZ * HID_SZ / 4;             // 262144
    const int bid = blockIdx.x, tid = threadIdx.x;

    if (bid < NT_BLK) {
        __shared__ float t[32][133];
        const int b0 = (bid % NBB) * 128;
        const int k0 = (bid / NBB) * 32;
#pragma unroll
        for (int i = 0; i < 4; i++) {
            const int idx = tid + i * 256;
            const int r = idx >> 5, cc = idx & 31;
            const float4 v = *reinterpret_cast<const float4*>(
                psp + (size_t)(k0 + r) * B_SZ + b0 + cc * 4);
            t[r][cc * 4 + 0] = v.x; t[r][cc * 4 + 1] = v.y;
            t[r][cc * 4 + 2] = v.z; t[r][cc * 4 + 3] = v.w;
        }
        __syncthreads();
#pragma unroll
        for (int i = 0; i < 2; i++) {
            const int idx = tid + i * 256;
            const int b = idx >> 2, kc = idx & 3;
            __half2 h[4];
#pragma unroll
            for (int j = 0; j < 4; j++)
                h[j] = __floats2half2_rn(t[kc * 8 + 2 * j][b], t[kc * 8 + 2 * j + 1][b]);
            *reinterpret_cast<uint4*>(g_At + (size_t)(b0 + b) * IN_SZ + k0 + kc * 8) =
                *reinterpret_cast<uint4*>(h);
        }
        return;
    }
    // weight convert: 4 float4s per thread, independent (MLP=4)
    const int base = (bid - NT_BLK) * 1024 + tid;
#pragma unroll
    for (int j = 0; j < 4; j++) {
        const int i = base + j * 256;
        const float4* src;
        __half* dst;
        int idx;
        if (i < N4H)            { src = Wh; dst = g_Wh; idx = i; }
        else if (i < N4H + N4O) { src = Wo; dst = g_Wo; idx = i - N4H; }
        else continue;
        const float4 v = src[idx];
        const __half2 h0 = __floats2half2_rn(v.x, v.y);
        const __half2 h1 = __floats2half2_rn(v.z, v.w);
        uint2 u;
        u.x = *reinterpret_cast<const uint32_t*>(&h0);
        u.y = *reinterpret_cast<const uint32_t*>(&h1);
        *reinterpret_cast<uint2*>(dst + (size_t)idx * 4) = u;
    }
}

// ---------------- launcher ----------------
extern "C" void kernel_launch(void* const* d_in, const int* in_sizes, int n_in,
                              void* d_out, int out_size) {
    const float* psp   = (const float*)d_in[0];  // [1024, 4096]
    const float* label = (const float*)d_in[1];  // [4096, 512]
    const float* W_h   = (const float*)d_in[2];  // [2048, 1024]
    const float* b_h   = (const float*)d_in[3];  // [2048]
    const float* W_o   = (const float*)d_in[4];  // [512, 2048]
    const float* b_o   = (const float*)d_in[5];  // [512]
    float* out = (float*)d_out;                  // [4096, 512]

    const int SMEM1 = 3 * 32768 + 64;            // stages + mbarriers
    const int SMEM2 = 3 * 24576 + 64;
    cudaFuncSetAttribute(k_gemm<IN_SZ, 0, 128>, cudaFuncAttributeMaxDynamicSharedMemorySize, SMEM1);
    cudaFuncSetAttribute(k_gemm<HID_SZ, 1, 64>, cudaFuncAttributeMaxDynamicSharedMemorySize, SMEM2);

    const int PREP_BLOCKS = (B_SZ / 128) * (IN_SZ / 32)
                          + (HID_SZ * IN_SZ / 4 + OUT_SZ * HID_SZ / 4 + 1023) / 1024;
    k_prep<<<PREP_BLOCKS, 256>>>(psp, (const float4*)W_h, (const float4*)W_o);

    k_gemm<IN_SZ,  0, 128><<<dim3(B_SZ / 128, HID_SZ / 128), 256, SMEM1>>>(b_h, nullptr, nullptr);
    k_gemm<HID_SZ, 1, 64 ><<<dim3(B_SZ / 64,  OUT_SZ / 128), 256, SMEM2>>>(b_o, label, out);
}